// round 9
// baseline (speedup 1.0000x reference)
#include <cuda_runtime.h>
#include <math.h>
#include <mma.h>

using namespace nvcuda;

#define B_   2
#define S_   2048
#define DM   4096
#define NH   32
#define NKV  8
#define HD   128
#define GRP  4
#define M_   (B_ * S_)        // 4096
#define KVDIM (NKV * HD)      // 1024

// ---------------- scratch (device globals; no allocation allowed) ----------
__device__ float g_Q [(size_t)M_ * DM];     // 64 MB (proj out, pre-rope)
__device__ float g_K [(size_t)M_ * KVDIM];  // 16 MB
__device__ float g_V [(size_t)M_ * KVDIM];  // 16 MB
__device__ float g_O [(size_t)M_ * DM];     // 64 MB (attention out)
__device__ float g_Qh[(size_t)M_ * DM];     // 64 MB  roped Q, tf32 hi
__device__ float g_Ql[(size_t)M_ * DM];     // 64 MB  roped Q, tf32 lo
__device__ float g_Kh[(size_t)M_ * KVDIM];  // 16 MB
__device__ float g_Kl[(size_t)M_ * KVDIM];  // 16 MB
__device__ float g_Vh[(size_t)M_ * KVDIM];  // 16 MB
__device__ float g_Vl[(size_t)M_ * KVDIM];  // 16 MB

__device__ __forceinline__ void tf32_split(float x, float& hi, float& lo) {
    hi = wmma::__float_to_tf32(x);
    lo = wmma::__float_to_tf32(x - hi);
}

// ---------------- 3xTF32 GEMM: C[M,N] = A[M,K] @ B[K,N], row-major ---------
// 128x128 CTA tile, BK=16, 256 threads (8 warps as 2x4), warp tile 64x32.
// hi/lo split staged in smem; 3 MMAs (AhBh + AhBl + AlBh) per tile pair.
#define GA_PART (128 * 20)     // floats per A buffer part
#define GB_PART (16 * 132)     // floats per B buffer part
#define GEMM_SMEM ((2 * GA_PART * 2 + 2 * GB_PART * 2) * 4)   // 74752 B

__global__ __launch_bounds__(256)
void tf32x3_gemm_kernel(const float* __restrict__ A, const float* __restrict__ B,
                        float* __restrict__ C, int M, int N, int K)
{
    extern __shared__ __align__(32) float dynsm[];
    float* Ah = dynsm;                    // [2][128][20]
    float* Al = Ah + 2 * GA_PART;
    float* Bh = Al + 2 * GA_PART;         // [2][16][132]
    float* Bl = Bh + 2 * GB_PART;

    const int tid  = threadIdx.x;
    const int warp = tid >> 5;
    const int wm   = warp >> 2;           // 0..1
    const int wn   = warp & 3;            // 0..3
    const int colBase = blockIdx.x * 128;
    const int rowBase = blockIdx.y * 128;

    const int a_r0 = (tid)       >> 2, a_c0 = ((tid)       & 3) << 2;
    const int a_r1 = (tid + 256) >> 2, a_c1 = ((tid + 256) & 3) << 2;
    const int b_r0 = (tid)       >> 5, b_c0 = ((tid)       & 31) << 2;
    const int b_r1 = (tid + 256) >> 5, b_c1 = ((tid + 256) & 31) << 2;

    wmma::fragment<wmma::accumulator, 16, 16, 8, float> acc[4][2];
#pragma unroll
    for (int i = 0; i < 4; i++)
#pragma unroll
        for (int j = 0; j < 2; j++) wmma::fill_fragment(acc[i][j], 0.0f);

    float4 aV0, aV1, bV0, bV1;

    // split+store one float4 into hi/lo smem arrays
#define SPLIT4(dstH, dstL, off, v) do {                                  \
        float h0,l0,h1,l1,h2,l2,h3,l3;                                    \
        tf32_split((v).x, h0, l0); tf32_split((v).y, h1, l1);             \
        tf32_split((v).z, h2, l2); tf32_split((v).w, h3, l3);             \
        *(float4*)((dstH) + (off)) = make_float4(h0, h1, h2, h3);         \
        *(float4*)((dstL) + (off)) = make_float4(l0, l1, l2, l3);         \
    } while (0)

    // prologue: tile 0 -> buffer 0
    aV0 = *(const float4*)(A + (size_t)(rowBase + a_r0) * K + a_c0);
    aV1 = *(const float4*)(A + (size_t)(rowBase + a_r1) * K + a_c1);
    bV0 = *(const float4*)(B + (size_t)b_r0 * N + colBase + b_c0);
    bV1 = *(const float4*)(B + (size_t)b_r1 * N + colBase + b_c1);
    SPLIT4(Ah, Al, a_r0 * 20 + a_c0, aV0);
    SPLIT4(Ah, Al, a_r1 * 20 + a_c1, aV1);
    SPLIT4(Bh, Bl, b_r0 * 132 + b_c0, bV0);
    SPLIT4(Bh, Bl, b_r1 * 132 + b_c1, bV1);
    __syncthreads();

    int buf = 0;
    const int nkt = K >> 4;
    for (int kt = 0; kt < nkt; kt++) {
        const int k1 = (kt + 1) << 4;
        const bool more = (kt + 1 < nkt);
        if (more) {   // prefetch next tile (overlaps mma)
            aV0 = *(const float4*)(A + (size_t)(rowBase + a_r0) * K + k1 + a_c0);
            aV1 = *(const float4*)(A + (size_t)(rowBase + a_r1) * K + k1 + a_c1);
            bV0 = *(const float4*)(B + (size_t)(k1 + b_r0) * N + colBase + b_c0);
            bV1 = *(const float4*)(B + (size_t)(k1 + b_r1) * N + colBase + b_c1);
        }
        const int aOff = buf * GA_PART + (wm * 64) * 20;
        const int bOff = buf * GB_PART + wn * 32;
#pragma unroll
        for (int ks = 0; ks < 16; ks += 8) {
            wmma::fragment<wmma::matrix_a, 16, 16, 8, wmma::precision::tf32, wmma::row_major> afh[4], afl[4];
            wmma::fragment<wmma::matrix_b, 16, 16, 8, wmma::precision::tf32, wmma::row_major> bfh[2], bfl[2];
#pragma unroll
            for (int i = 0; i < 4; i++) {
                wmma::load_matrix_sync(afh[i], Ah + aOff + i * 16 * 20 + ks, 20);
                wmma::load_matrix_sync(afl[i], Al + aOff + i * 16 * 20 + ks, 20);
            }
#pragma unroll
            for (int j = 0; j < 2; j++) {
                wmma::load_matrix_sync(bfh[j], Bh + bOff + ks * 132 + j * 16, 132);
                wmma::load_matrix_sync(bfl[j], Bl + bOff + ks * 132 + j * 16, 132);
            }
#pragma unroll
            for (int i = 0; i < 4; i++)
#pragma unroll
                for (int j = 0; j < 2; j++) {
                    wmma::mma_sync(acc[i][j], afh[i], bfh[j], acc[i][j]);
                    wmma::mma_sync(acc[i][j], afh[i], bfl[j], acc[i][j]);
                    wmma::mma_sync(acc[i][j], afl[i], bfh[j], acc[i][j]);
                }
        }
        if (more) {
            const int nb = buf ^ 1;
            SPLIT4(Ah, Al, nb * GA_PART + a_r0 * 20 + a_c0, aV0);
            SPLIT4(Ah, Al, nb * GA_PART + a_r1 * 20 + a_c1, aV1);
            SPLIT4(Bh, Bl, nb * GB_PART + b_r0 * 132 + b_c0, bV0);
            SPLIT4(Bh, Bl, nb * GB_PART + b_r1 * 132 + b_c1, bV1);
            __syncthreads();
            buf = nb;
        }
    }
#undef SPLIT4

#pragma unroll
    for (int i = 0; i < 4; i++)
#pragma unroll
        for (int j = 0; j < 2; j++)
            wmma::store_matrix_sync(
                C + (size_t)(rowBase + wm * 64 + i * 16) * N + colBase + wn * 32 + j * 16,
                acc[i][j], N, wmma::mem_row_major);
}

// ---------------- RoPE + tf32 hi/lo split ----------------------------------
__global__ void rope_split_kernel(const float* __restrict__ src,
                                  float* __restrict__ dstH, float* __restrict__ dstL,
                                  int ld, int nheads, int total)
{
    int idx = blockIdx.x * blockDim.x + threadIdx.x;
    if (idx >= total) return;
    int i   = idx & 63;          // pair index 0..63
    int t   = idx >> 6;
    int h   = t % nheads;
    int row = t / nheads;        // b*S + s
    int s   = row & (S_ - 1);

    float inv = powf(10000.0f, -(float)i * (1.0f / 64.0f));
    float ang = (float)s * inv;
    float sn, cs;
    sincosf(ang, &sn, &cs);

    size_t base = (size_t)row * ld + h * HD + i;
    float x1 = src[base], x2 = src[base + 64];
    float r1 = x1 * cs - x2 * sn;
    float r2 = x2 * cs + x1 * sn;
    float h1, l1, h2, l2;
    tf32_split(r1, h1, l1);
    tf32_split(r2, h2, l2);
    dstH[base] = h1;  dstL[base] = l1;
    dstH[base + 64] = h2;  dstL[base + 64] = l2;
}

// ---------------- plain tf32 hi/lo split (for V) ----------------------------
__global__ void split_kernel(const float* __restrict__ src,
                             float* __restrict__ dstH, float* __restrict__ dstL,
                             int total)
{
    int idx = blockIdx.x * blockDim.x + threadIdx.x;
    if (idx >= total) return;
    float h, l;
    tf32_split(src[idx], h, l);
    dstH[idx] = h;
    dstL[idx] = l;
}

// ---------------- 3xTF32 wmma flash attention (causal GQA) ------------------
// CTA: 64 queries of one (b,h). 8 warps (256 thr).
// QK^T: 3 MMAs (QhKh + QhKl + QlKh).  PV: 2 MMAs (P Vh + P Vl), P tf32-rounded.
#define PS_LD 68
#define OS_LD 128
#define ATTN_SMEM ((64 * PS_LD + 64 * OS_LD) * 4)

__global__ __launch_bounds__(256)
void attn_kernel(const float* __restrict__ Qh, const float* __restrict__ Ql,
                 const float* __restrict__ Kh, const float* __restrict__ Kl,
                 const float* __restrict__ Vh, const float* __restrict__ Vl,
                 float* __restrict__ O)
{
    extern __shared__ __align__(256) float dynsm[];
    float* Ps = dynsm;                 // [64][PS_LD]
    float* Os = dynsm + 64 * PS_LD;    // [64][OS_LD]

    const int qt  = gridDim.x - 1 - blockIdx.x;   // heavy tiles first
    const int q0  = qt * 64;
    const int h   = blockIdx.y;
    const int b   = blockIdx.z;
    const int kvh = h / GRP;
    const int tid = threadIdx.x;
    const int w   = tid >> 5;
    const int wr  = w >> 1;            // 0..3
    const int wc  = w & 1;             // 0..1

    const int srow = tid >> 2;         // softmax row 0..63
    const int sgrp = tid & 3;          // 4 threads per row

    const float scale = 0.08838834764831845f;  // 128^-0.5

    const size_t qoff = (size_t)(b * S_ + q0 + wr * 16) * DM + h * HD;
    const float* Qph = Qh + qoff;
    const float* Qpl = Ql + qoff;
    const size_t kvoff = (size_t)(b * S_) * KVDIM + kvh * HD;
    const float* Khp = Kh + kvoff;
    const float* Klp = Kl + kvoff;
    const float* Vhp = Vh + kvoff;
    const float* Vlp = Vl + kvoff;

    // zero O accumulator
    for (int i = tid; i < 64 * OS_LD; i += 256) Os[i] = 0.f;
    __syncthreads();

    float mrow = -INFINITY, lrow = 0.f;

    const int nkt = qt + 1;
    for (int kt = 0; kt < nkt; kt++) {
        const int c0 = kt * 64;

        // ---- scores: S[64x64] = Q Ktile^T, 3xTF32 ----
        {
            wmma::fragment<wmma::accumulator, 16, 16, 8, float> sacc[2];
            wmma::fill_fragment(sacc[0], 0.f);
            wmma::fill_fragment(sacc[1], 0.f);
#pragma unroll
            for (int d0 = 0; d0 < HD; d0 += 8) {
                wmma::fragment<wmma::matrix_a, 16, 16, 8, wmma::precision::tf32, wmma::row_major> afh, afl;
                wmma::load_matrix_sync(afh, Qph + d0, DM);
                wmma::load_matrix_sync(afl, Qpl + d0, DM);
#pragma unroll
                for (int j = 0; j < 2; j++) {
                    wmma::fragment<wmma::matrix_b, 16, 16, 8, wmma::precision::tf32, wmma::col_major> bfh, bfl;
                    size_t koff = (size_t)(c0 + wc * 32 + j * 16) * KVDIM + d0;
                    wmma::load_matrix_sync(bfh, Khp + koff, KVDIM);
                    wmma::load_matrix_sync(bfl, Klp + koff, KVDIM);
                    wmma::mma_sync(sacc[j], afh, bfh, sacc[j]);
                    wmma::mma_sync(sacc[j], afh, bfl, sacc[j]);
                    wmma::mma_sync(sacc[j], afl, bfh, sacc[j]);
                }
            }
#pragma unroll
            for (int j = 0; j < 2; j++)
                wmma::store_matrix_sync(&Ps[(wr * 16) * PS_LD + wc * 32 + j * 16],
                                        sacc[j], PS_LD, wmma::mem_row_major);
        }
        __syncthreads();

        // ---- softmax (SIMT, online): 4 threads per row, 16 cols each ----
        {
            const bool diag = (kt == nkt - 1);
            float sv[16];
            float* prow = &Ps[srow * PS_LD + sgrp * 16];
#pragma unroll
            for (int u = 0; u < 16; u++) {
                float x = prow[u] * scale;
                if (diag && (c0 + sgrp * 16 + u > q0 + srow)) x = -INFINITY;
                sv[u] = x;
            }
            float mloc = sv[0];
#pragma unroll
            for (int u = 1; u < 16; u++) mloc = fmaxf(mloc, sv[u]);
            mloc = fmaxf(mloc, __shfl_xor_sync(0xffffffffu, mloc, 1));
            mloc = fmaxf(mloc, __shfl_xor_sync(0xffffffffu, mloc, 2));
            float mnew = fmaxf(mrow, mloc);
            float corr = __expf(mrow - mnew);
            float rs = 0.f;
#pragma unroll
            for (int u = 0; u < 16; u++) {
                float p = wmma::__float_to_tf32(__expf(sv[u] - mnew));  // consistent with HMMA
                prow[u] = p;
                rs += p;
            }
            rs += __shfl_xor_sync(0xffffffffu, rs, 1);
            rs += __shfl_xor_sync(0xffffffffu, rs, 2);
            lrow = lrow * corr + rs;
            mrow = mnew;
            // rescale O accumulator row
            float4* orow = (float4*)&Os[srow * OS_LD + sgrp * 32];
#pragma unroll
            for (int u = 0; u < 8; u++) {
                float4 t = orow[u];
                t.x *= corr; t.y *= corr; t.z *= corr; t.w *= corr;
                orow[u] = t;
            }
        }
        __syncthreads();

        // ---- O += P @ Vtile (P tf32, V split hi/lo: 2 MMAs) ----
        {
            wmma::fragment<wmma::accumulator, 16, 16, 8, float> oacc[4];
#pragma unroll
            for (int j = 0; j < 4; j++)
                wmma::load_matrix_sync(oacc[j],
                    &Os[(wr * 16) * OS_LD + (w & 1) * 64 + j * 16], OS_LD,
                    wmma::mem_row_major);
#pragma unroll
            for (int kk = 0; kk < 64; kk += 8) {
                wmma::fragment<wmma::matrix_a, 16, 16, 8, wmma::precision::tf32, wmma::row_major> pa;
                wmma::load_matrix_sync(pa, &Ps[(wr * 16) * PS_LD + kk], PS_LD);
#pragma unroll
                for (int j = 0; j < 4; j++) {
                    wmma::fragment<wmma::matrix_b, 16, 16, 8, wmma::precision::tf32, wmma::row_major> vbh, vbl;
                    size_t voff = (size_t)(c0 + kk) * KVDIM + (w & 1) * 64 + j * 16;
                    wmma::load_matrix_sync(vbh, Vhp + voff, KVDIM);
                    wmma::load_matrix_sync(vbl, Vlp + voff, KVDIM);
                    wmma::mma_sync(oacc[j], pa, vbh, oacc[j]);
                    wmma::mma_sync(oacc[j], pa, vbl, oacc[j]);
                }
            }
#pragma unroll
            for (int j = 0; j < 4; j++)
                wmma::store_matrix_sync(
                    &Os[(wr * 16) * OS_LD + (w & 1) * 64 + j * 16], oacc[j], OS_LD,
                    wmma::mem_row_major);
        }
        __syncthreads();
    }

    // ---- normalize + store O in [b*s, h*128+d] layout ----
    {
        float inv = 1.0f / lrow;
        float* dst = O + (size_t)(b * S_ + q0 + srow) * DM + h * HD + sgrp * 32;
        float4* orow = (float4*)&Os[srow * OS_LD + sgrp * 32];
#pragma unroll
        for (int u = 0; u < 8; u++) {
            float4 t = orow[u];
            t.x *= inv; t.y *= inv; t.z *= inv; t.w *= inv;
            ((float4*)dst)[u] = t;
        }
    }
}

// ---------------- launch ----------------------------------------------------
extern "C" void kernel_launch(void* const* d_in, const int* in_sizes, int n_in,
                              void* d_out, int out_size)
{
    const float* x  = (const float*)d_in[0];
    // d_in[1] = mask (deterministic causal triu; computed analytically instead)
    const float* Wq = (const float*)d_in[2];
    const float* Wk = (const float*)d_in[3];
    const float* Wv = (const float*)d_in[4];
    const float* Wo = (const float*)d_in[5];
    float* out = (float*)d_out;

    float *Qb, *Kb, *Vb, *Ob, *Qhb, *Qlb, *Khb, *Klb, *Vhb, *Vlb;
    cudaGetSymbolAddress((void**)&Qb,  g_Q);
    cudaGetSymbolAddress((void**)&Kb,  g_K);
    cudaGetSymbolAddress((void**)&Vb,  g_V);
    cudaGetSymbolAddress((void**)&Ob,  g_O);
    cudaGetSymbolAddress((void**)&Qhb, g_Qh);
    cudaGetSymbolAddress((void**)&Qlb, g_Ql);
    cudaGetSymbolAddress((void**)&Khb, g_Kh);
    cudaGetSymbolAddress((void**)&Klb, g_Kl);
    cudaGetSymbolAddress((void**)&Vhb, g_Vh);
    cudaGetSymbolAddress((void**)&Vlb, g_Vl);

    static bool attrs_set = false;
    if (!attrs_set) {   // host-side state, not stream work; capture-safe
        cudaFuncSetAttribute(attn_kernel,
                             cudaFuncAttributeMaxDynamicSharedMemorySize, ATTN_SMEM);
        cudaFuncSetAttribute(tf32x3_gemm_kernel,
                             cudaFuncAttributeMaxDynamicSharedMemorySize, GEMM_SMEM);
        attrs_set = true;
    }

    // projections (3xTF32 tensor cores)
    tf32x3_gemm_kernel<<<dim3(DM / 128, M_ / 128), 256, GEMM_SMEM>>>(x, Wq, Qb, M_, DM, DM);
    tf32x3_gemm_kernel<<<dim3(KVDIM / 128, M_ / 128), 256, GEMM_SMEM>>>(x, Wk, Kb, M_, KVDIM, DM);
    tf32x3_gemm_kernel<<<dim3(KVDIM / 128, M_ / 128), 256, GEMM_SMEM>>>(x, Wv, Vb, M_, KVDIM, DM);

    // RoPE + hi/lo split; V split
    {
        int totQ = M_ * NH * 64;
        rope_split_kernel<<<(totQ + 255) / 256, 256>>>(Qb, Qhb, Qlb, DM, NH, totQ);
        int totK = M_ * NKV * 64;
        rope_split_kernel<<<(totK + 255) / 256, 256>>>(Kb, Khb, Klb, KVDIM, NKV, totK);
        int totV = M_ * KVDIM;
        split_kernel<<<(totV + 255) / 256, 256>>>(Vb, Vhb, Vlb, totV);
    }

    // causal GQA attention (3xTF32)
    attn_kernel<<<dim3(S_ / 64, NH, B_), 256, ATTN_SMEM>>>(Qhb, Qlb, Khb, Klb, Vhb, Vlb, Ob);

    // output projection (3xTF32)
    tf32x3_gemm_kernel<<<dim3(DM / 128, M_ / 128), 256, GEMM_SMEM>>>(Ob, Wo, out, M_, DM, DM);
}

// round 11
// speedup vs baseline: 1.1251x; 1.1251x over previous
#include <cuda_runtime.h>
#include <math.h>
#include <mma.h>

using namespace nvcuda;

#define B_   2
#define S_   2048
#define DM   4096
#define NH   32
#define NKV  8
#define HD   128
#define GRP  4
#define M_   (B_ * S_)        // 4096
#define KVDIM (NKV * HD)      // 1024

// ---------------- scratch (device globals; no allocation allowed) ----------
__device__ float g_Q [(size_t)M_ * DM];     // 64 MB (proj out, pre-rope)
__device__ float g_K [(size_t)M_ * KVDIM];  // 16 MB
__device__ float g_V [(size_t)M_ * KVDIM];  // 16 MB
__device__ float g_O [(size_t)M_ * DM];     // 64 MB (attention out)
__device__ float g_Qh[(size_t)M_ * DM];     // 64 MB  roped Q, tf32 hi
__device__ float g_Ql[(size_t)M_ * DM];     // 64 MB  roped Q, tf32 lo
__device__ float g_Kh[(size_t)M_ * KVDIM];  // 16 MB
__device__ float g_Kl[(size_t)M_ * KVDIM];  // 16 MB
__device__ float g_Vh[(size_t)M_ * KVDIM];  // 16 MB
__device__ float g_Vl[(size_t)M_ * KVDIM];  // 16 MB

__device__ __forceinline__ void tf32_split(float x, float& hi, float& lo) {
    hi = wmma::__float_to_tf32(x);
    lo = wmma::__float_to_tf32(x - hi);
}

// ---------------- 3xTF32 GEMM: C[M,N] = A[M,K] @ B[K,N], row-major ---------
// (unchanged from R9 passing kernel)
#define GA_PART (128 * 20)     // floats per A buffer part
#define GB_PART (16 * 132)     // floats per B buffer part
#define GEMM_SMEM ((2 * GA_PART * 2 + 2 * GB_PART * 2) * 4)   // 74752 B

__global__ __launch_bounds__(256)
void tf32x3_gemm_kernel(const float* __restrict__ A, const float* __restrict__ B,
                        float* __restrict__ C, int M, int N, int K)
{
    extern __shared__ __align__(32) float dynsm[];
    float* Ah = dynsm;                    // [2][128][20]
    float* Al = Ah + 2 * GA_PART;
    float* Bh = Al + 2 * GA_PART;         // [2][16][132]
    float* Bl = Bh + 2 * GB_PART;

    const int tid  = threadIdx.x;
    const int warp = tid >> 5;
    const int wm   = warp >> 2;           // 0..1
    const int wn   = warp & 3;            // 0..3
    const int colBase = blockIdx.x * 128;
    const int rowBase = blockIdx.y * 128;

    const int a_r0 = (tid)       >> 2, a_c0 = ((tid)       & 3) << 2;
    const int a_r1 = (tid + 256) >> 2, a_c1 = ((tid + 256) & 3) << 2;
    const int b_r0 = (tid)       >> 5, b_c0 = ((tid)       & 31) << 2;
    const int b_r1 = (tid + 256) >> 5, b_c1 = ((tid + 256) & 31) << 2;

    wmma::fragment<wmma::accumulator, 16, 16, 8, float> acc[4][2];
#pragma unroll
    for (int i = 0; i < 4; i++)
#pragma unroll
        for (int j = 0; j < 2; j++) wmma::fill_fragment(acc[i][j], 0.0f);

    float4 aV0, aV1, bV0, bV1;

#define SPLIT4(dstH, dstL, off, v) do {                                  \
        float h0,l0,h1,l1,h2,l2,h3,l3;                                    \
        tf32_split((v).x, h0, l0); tf32_split((v).y, h1, l1);             \
        tf32_split((v).z, h2, l2); tf32_split((v).w, h3, l3);             \
        *(float4*)((dstH) + (off)) = make_float4(h0, h1, h2, h3);         \
        *(float4*)((dstL) + (off)) = make_float4(l0, l1, l2, l3);         \
    } while (0)

    aV0 = *(const float4*)(A + (size_t)(rowBase + a_r0) * K + a_c0);
    aV1 = *(const float4*)(A + (size_t)(rowBase + a_r1) * K + a_c1);
    bV0 = *(const float4*)(B + (size_t)b_r0 * N + colBase + b_c0);
    bV1 = *(const float4*)(B + (size_t)b_r1 * N + colBase + b_c1);
    SPLIT4(Ah, Al, a_r0 * 20 + a_c0, aV0);
    SPLIT4(Ah, Al, a_r1 * 20 + a_c1, aV1);
    SPLIT4(Bh, Bl, b_r0 * 132 + b_c0, bV0);
    SPLIT4(Bh, Bl, b_r1 * 132 + b_c1, bV1);
    __syncthreads();

    int buf = 0;
    const int nkt = K >> 4;
    for (int kt = 0; kt < nkt; kt++) {
        const int k1 = (kt + 1) << 4;
        const bool more = (kt + 1 < nkt);
        if (more) {
            aV0 = *(const float4*)(A + (size_t)(rowBase + a_r0) * K + k1 + a_c0);
            aV1 = *(const float4*)(A + (size_t)(rowBase + a_r1) * K + k1 + a_c1);
            bV0 = *(const float4*)(B + (size_t)(k1 + b_r0) * N + colBase + b_c0);
            bV1 = *(const float4*)(B + (size_t)(k1 + b_r1) * N + colBase + b_c1);
        }
        const int aOff = buf * GA_PART + (wm * 64) * 20;
        const int bOff = buf * GB_PART + wn * 32;
#pragma unroll
        for (int ks = 0; ks < 16; ks += 8) {
            wmma::fragment<wmma::matrix_a, 16, 16, 8, wmma::precision::tf32, wmma::row_major> afh[4], afl[4];
            wmma::fragment<wmma::matrix_b, 16, 16, 8, wmma::precision::tf32, wmma::row_major> bfh[2], bfl[2];
#pragma unroll
            for (int i = 0; i < 4; i++) {
                wmma::load_matrix_sync(afh[i], Ah + aOff + i * 16 * 20 + ks, 20);
                wmma::load_matrix_sync(afl[i], Al + aOff + i * 16 * 20 + ks, 20);
            }
#pragma unroll
            for (int j = 0; j < 2; j++) {
                wmma::load_matrix_sync(bfh[j], Bh + bOff + ks * 132 + j * 16, 132);
                wmma::load_matrix_sync(bfl[j], Bl + bOff + ks * 132 + j * 16, 132);
            }
#pragma unroll
            for (int i = 0; i < 4; i++)
#pragma unroll
                for (int j = 0; j < 2; j++) {
                    wmma::mma_sync(acc[i][j], afh[i], bfh[j], acc[i][j]);
                    wmma::mma_sync(acc[i][j], afh[i], bfl[j], acc[i][j]);
                    wmma::mma_sync(acc[i][j], afl[i], bfh[j], acc[i][j]);
                }
        }
        if (more) {
            const int nb = buf ^ 1;
            SPLIT4(Ah, Al, nb * GA_PART + a_r0 * 20 + a_c0, aV0);
            SPLIT4(Ah, Al, nb * GA_PART + a_r1 * 20 + a_c1, aV1);
            SPLIT4(Bh, Bl, nb * GB_PART + b_r0 * 132 + b_c0, bV0);
            SPLIT4(Bh, Bl, nb * GB_PART + b_r1 * 132 + b_c1, bV1);
            __syncthreads();
            buf = nb;
        }
    }
#undef SPLIT4

#pragma unroll
    for (int i = 0; i < 4; i++)
#pragma unroll
        for (int j = 0; j < 2; j++)
            wmma::store_matrix_sync(
                C + (size_t)(rowBase + wm * 64 + i * 16) * N + colBase + wn * 32 + j * 16,
                acc[i][j], N, wmma::mem_row_major);
}

// ---------------- RoPE + tf32 hi/lo split ----------------------------------
__global__ void rope_split_kernel(const float* __restrict__ src,
                                  float* __restrict__ dstH, float* __restrict__ dstL,
                                  int ld, int nheads, int total)
{
    int idx = blockIdx.x * blockDim.x + threadIdx.x;
    if (idx >= total) return;
    int i   = idx & 63;
    int t   = idx >> 6;
    int h   = t % nheads;
    int row = t / nheads;
    int s   = row & (S_ - 1);

    float inv = powf(10000.0f, -(float)i * (1.0f / 64.0f));
    float ang = (float)s * inv;
    float sn, cs;
    sincosf(ang, &sn, &cs);

    size_t base = (size_t)row * ld + h * HD + i;
    float x1 = src[base], x2 = src[base + 64];
    float r1 = x1 * cs - x2 * sn;
    float r2 = x2 * cs + x1 * sn;
    float h1, l1, h2, l2;
    tf32_split(r1, h1, l1);
    tf32_split(r2, h2, l2);
    dstH[base] = h1;  dstL[base] = l1;
    dstH[base + 64] = h2;  dstL[base + 64] = l2;
}

// ---------------- plain tf32 hi/lo split (for V) ----------------------------
__global__ void split_kernel(const float* __restrict__ src,
                             float* __restrict__ dstH, float* __restrict__ dstL,
                             int total)
{
    int idx = blockIdx.x * blockDim.x + threadIdx.x;
    if (idx >= total) return;
    float h, l;
    tf32_split(src[idx], h, l);
    dstH[idx] = h;
    dstL[idx] = l;
}

// ---------------- 3xTF32 wmma flash attention, smem-staged ------------------
// CTA: 64 queries of one (b,h). 8 warps.
// Q hi/lo staged once (64x132 each); K tile staged per iter, V reuses the
// same buffers after softmax. Same MMA sequence/operands as R9 (bit-exact).
#define QS_LD 132
#define PS_LD 68
#define OS_LD 128
#define ATTN_SMEM ((4 * 64 * QS_LD + 64 * PS_LD + 64 * OS_LD) * 4)   // 185344 B

__global__ __launch_bounds__(256)
void attn_kernel(const float* __restrict__ Qh, const float* __restrict__ Ql,
                 const float* __restrict__ Kh, const float* __restrict__ Kl,
                 const float* __restrict__ Vh, const float* __restrict__ Vl,
                 float* __restrict__ O)
{
    extern __shared__ __align__(256) float dynsm[];
    float* Qsh = dynsm;                  // [64][QS_LD]
    float* Qsl = Qsh + 64 * QS_LD;       // [64][QS_LD]
    float* KVh = Qsl + 64 * QS_LD;       // [64][QS_LD]  K tile, then V tile
    float* KVl = KVh + 64 * QS_LD;       // [64][QS_LD]
    float* Ps  = KVl + 64 * QS_LD;       // [64][PS_LD]
    float* Os  = Ps  + 64 * PS_LD;       // [64][OS_LD]

    const int qt  = gridDim.x - 1 - blockIdx.x;   // heavy tiles first
    const int q0  = qt * 64;
    const int h   = blockIdx.y;
    const int b   = blockIdx.z;
    const int kvh = h / GRP;
    const int tid = threadIdx.x;
    const int w   = tid >> 5;
    const int wr  = w >> 1;            // 0..3
    const int wc  = w & 1;             // 0..1

    const int srow = tid >> 2;         // softmax row 0..63
    const int sgrp = tid & 3;          // 4 threads per row

    const float scale = 0.08838834764831845f;  // 128^-0.5

    const size_t kvoff = (size_t)(b * S_) * KVDIM + kvh * HD;
    const float* Khp = Kh + kvoff;
    const float* Klp = Kl + kvoff;
    const float* Vhp = Vh + kvoff;
    const float* Vlp = Vl + kvoff;

    // per-thread staging coords: 64 rows x 32 float4 = 2048 float4, 8 per thread
    const int ld_row = tid >> 2;             // 0..63
    const int ld_c0  = (tid & 3) << 5;       // 0,32,64,96 (float index), 8 float4 each

    // ---- stage Q hi/lo once (coalesced) ----
    {
        const size_t qgbase = (size_t)(b * S_ + q0 + ld_row) * DM + h * HD + ld_c0;
#pragma unroll
        for (int u = 0; u < 8; u++) {
            *(float4*)(Qsh + ld_row * QS_LD + ld_c0 + u * 4) =
                *(const float4*)(Qh + qgbase + u * 4);
            *(float4*)(Qsl + ld_row * QS_LD + ld_c0 + u * 4) =
                *(const float4*)(Ql + qgbase + u * 4);
        }
    }
    // zero O accumulator
    for (int i = tid; i < 64 * OS_LD; i += 256) Os[i] = 0.f;
    __syncthreads();

    float mrow = -INFINITY, lrow = 0.f;

    const int nkt = qt + 1;
    for (int kt = 0; kt < nkt; kt++) {
        const int c0 = kt * 64;

        // ---- stage K tile hi/lo (coalesced) ----
        {
            const size_t kgbase = (size_t)(c0 + ld_row) * KVDIM + ld_c0;
#pragma unroll
            for (int u = 0; u < 8; u++) {
                *(float4*)(KVh + ld_row * QS_LD + ld_c0 + u * 4) =
                    *(const float4*)(Khp + kgbase + u * 4);
                *(float4*)(KVl + ld_row * QS_LD + ld_c0 + u * 4) =
                    *(const float4*)(Klp + kgbase + u * 4);
            }
        }
        __syncthreads();

        // ---- scores: S[64x64] = Q Ktile^T, 3xTF32 (fragments from smem) ----
        {
            wmma::fragment<wmma::accumulator, 16, 16, 8, float> sacc[2];
            wmma::fill_fragment(sacc[0], 0.f);
            wmma::fill_fragment(sacc[1], 0.f);
#pragma unroll
            for (int d0 = 0; d0 < HD; d0 += 8) {
                wmma::fragment<wmma::matrix_a, 16, 16, 8, wmma::precision::tf32, wmma::row_major> afh, afl;
                wmma::load_matrix_sync(afh, Qsh + (wr * 16) * QS_LD + d0, QS_LD);
                wmma::load_matrix_sync(afl, Qsl + (wr * 16) * QS_LD + d0, QS_LD);
#pragma unroll
                for (int j = 0; j < 2; j++) {
                    wmma::fragment<wmma::matrix_b, 16, 16, 8, wmma::precision::tf32, wmma::col_major> bfh, bfl;
                    const int ko = (wc * 32 + j * 16) * QS_LD + d0;
                    wmma::load_matrix_sync(bfh, KVh + ko, QS_LD);
                    wmma::load_matrix_sync(bfl, KVl + ko, QS_LD);
                    wmma::mma_sync(sacc[j], afh, bfh, sacc[j]);
                    wmma::mma_sync(sacc[j], afh, bfl, sacc[j]);
                    wmma::mma_sync(sacc[j], afl, bfh, sacc[j]);
                }
            }
#pragma unroll
            for (int j = 0; j < 2; j++)
                wmma::store_matrix_sync(&Ps[(wr * 16) * PS_LD + wc * 32 + j * 16],
                                        sacc[j], PS_LD, wmma::mem_row_major);
        }
        __syncthreads();

        // ---- softmax (SIMT, online): 4 threads per row, 16 cols each ----
        {
            const bool diag = (kt == nkt - 1);
            float sv[16];
            float* prow = &Ps[srow * PS_LD + sgrp * 16];
#pragma unroll
            for (int u = 0; u < 16; u++) {
                float x = prow[u] * scale;
                if (diag && (c0 + sgrp * 16 + u > q0 + srow)) x = -INFINITY;
                sv[u] = x;
            }
            float mloc = sv[0];
#pragma unroll
            for (int u = 1; u < 16; u++) mloc = fmaxf(mloc, sv[u]);
            mloc = fmaxf(mloc, __shfl_xor_sync(0xffffffffu, mloc, 1));
            mloc = fmaxf(mloc, __shfl_xor_sync(0xffffffffu, mloc, 2));
            float mnew = fmaxf(mrow, mloc);
            float corr = __expf(mrow - mnew);
            float rs = 0.f;
#pragma unroll
            for (int u = 0; u < 16; u++) {
                float p = wmma::__float_to_tf32(__expf(sv[u] - mnew));
                prow[u] = p;
                rs += p;
            }
            rs += __shfl_xor_sync(0xffffffffu, rs, 1);
            rs += __shfl_xor_sync(0xffffffffu, rs, 2);
            lrow = lrow * corr + rs;
            mrow = mnew;
            float4* orow = (float4*)&Os[srow * OS_LD + sgrp * 32];
#pragma unroll
            for (int u = 0; u < 8; u++) {
                float4 t = orow[u];
                t.x *= corr; t.y *= corr; t.z *= corr; t.w *= corr;
                orow[u] = t;
            }
        }
        __syncthreads();   // softmax done; also all QK reads of KVh/KVl done

        // ---- stage V tile hi/lo into the same buffers ----
        {
            const size_t vgbase = (size_t)(c0 + ld_row) * KVDIM + ld_c0;
#pragma unroll
            for (int u = 0; u < 8; u++) {
                *(float4*)(KVh + ld_row * QS_LD + ld_c0 + u * 4) =
                    *(const float4*)(Vhp + vgbase + u * 4);
                *(float4*)(KVl + ld_row * QS_LD + ld_c0 + u * 4) =
                    *(const float4*)(Vlp + vgbase + u * 4);
            }
        }
        __syncthreads();

        // ---- O += P @ Vtile (P tf32, V hi/lo: 2 MMAs; fragments from smem) ----
        {
            wmma::fragment<wmma::accumulator, 16, 16, 8, float> oacc[4];
#pragma unroll
            for (int j = 0; j < 4; j++)
                wmma::load_matrix_sync(oacc[j],
                    &Os[(wr * 16) * OS_LD + (w & 1) * 64 + j * 16], OS_LD,
                    wmma::mem_row_major);
#pragma unroll
            for (int kk = 0; kk < 64; kk += 8) {
                wmma::fragment<wmma::matrix_a, 16, 16, 8, wmma::precision::tf32, wmma::row_major> pa;
                wmma::load_matrix_sync(pa, &Ps[(wr * 16) * PS_LD + kk], PS_LD);
#pragma unroll
                for (int j = 0; j < 4; j++) {
                    wmma::fragment<wmma::matrix_b, 16, 16, 8, wmma::precision::tf32, wmma::row_major> vbh, vbl;
                    const int vo = kk * QS_LD + (w & 1) * 64 + j * 16;
                    wmma::load_matrix_sync(vbh, KVh + vo, QS_LD);
                    wmma::load_matrix_sync(vbl, KVl + vo, QS_LD);
                    wmma::mma_sync(oacc[j], pa, vbh, oacc[j]);
                    wmma::mma_sync(oacc[j], pa, vbl, oacc[j]);
                }
            }
#pragma unroll
            for (int j = 0; j < 4; j++)
                wmma::store_matrix_sync(
                    &Os[(wr * 16) * OS_LD + (w & 1) * 64 + j * 16], oacc[j], OS_LD,
                    wmma::mem_row_major);
        }
        __syncthreads();   // PV reads of KVh/KVl done; safe to overwrite next iter
    }

    // ---- normalize + store O in [b*s, h*128+d] layout ----
    {
        float inv = 1.0f / lrow;
        float* dst = O + (size_t)(b * S_ + q0 + srow) * DM + h * HD + sgrp * 32;
        float4* orow = (float4*)&Os[srow * OS_LD + sgrp * 32];
#pragma unroll
        for (int u = 0; u < 8; u++) {
            float4 t = orow[u];
            t.x *= inv; t.y *= inv; t.z *= inv; t.w *= inv;
            ((float4*)dst)[u] = t;
        }
    }
}

// ---------------- launch ----------------------------------------------------
extern "C" void kernel_launch(void* const* d_in, const int* in_sizes, int n_in,
                              void* d_out, int out_size)
{
    const float* x  = (const float*)d_in[0];
    // d_in[1] = mask (deterministic causal triu; computed analytically instead)
    const float* Wq = (const float*)d_in[2];
    const float* Wk = (const float*)d_in[3];
    const float* Wv = (const float*)d_in[4];
    const float* Wo = (const float*)d_in[5];
    float* out = (float*)d_out;

    float *Qb, *Kb, *Vb, *Ob, *Qhb, *Qlb, *Khb, *Klb, *Vhb, *Vlb;
    cudaGetSymbolAddress((void**)&Qb,  g_Q);
    cudaGetSymbolAddress((void**)&Kb,  g_K);
    cudaGetSymbolAddress((void**)&Vb,  g_V);
    cudaGetSymbolAddress((void**)&Ob,  g_O);
    cudaGetSymbolAddress((void**)&Qhb, g_Qh);
    cudaGetSymbolAddress((void**)&Qlb, g_Ql);
    cudaGetSymbolAddress((void**)&Khb, g_Kh);
    cudaGetSymbolAddress((void**)&Klb, g_Kl);
    cudaGetSymbolAddress((void**)&Vhb, g_Vh);
    cudaGetSymbolAddress((void**)&Vlb, g_Vl);

    static bool attrs_set = false;
    if (!attrs_set) {   // host-side state, not stream work; capture-safe
        cudaFuncSetAttribute(attn_kernel,
                             cudaFuncAttributeMaxDynamicSharedMemorySize, ATTN_SMEM);
        cudaFuncSetAttribute(tf32x3_gemm_kernel,
                             cudaFuncAttributeMaxDynamicSharedMemorySize, GEMM_SMEM);
        attrs_set = true;
    }

    // projections (3xTF32 tensor cores)
    tf32x3_gemm_kernel<<<dim3(DM / 128, M_ / 128), 256, GEMM_SMEM>>>(x, Wq, Qb, M_, DM, DM);
    tf32x3_gemm_kernel<<<dim3(KVDIM / 128, M_ / 128), 256, GEMM_SMEM>>>(x, Wk, Kb, M_, KVDIM, DM);
    tf32x3_gemm_kernel<<<dim3(KVDIM / 128, M_ / 128), 256, GEMM_SMEM>>>(x, Wv, Vb, M_, KVDIM, DM);

    // RoPE + hi/lo split; V split
    {
        int totQ = M_ * NH * 64;
        rope_split_kernel<<<(totQ + 255) / 256, 256>>>(Qb, Qhb, Qlb, DM, NH, totQ);
        int totK = M_ * NKV * 64;
        rope_split_kernel<<<(totK + 255) / 256, 256>>>(Kb, Khb, Klb, KVDIM, NKV, totK);
        int totV = M_ * KVDIM;
        split_kernel<<<(totV + 255) / 256, 256>>>(Vb, Vhb, Vlb, totV);
    }

    // causal GQA attention (3xTF32, smem-staged)
    attn_kernel<<<dim3(S_ / 64, NH, B_), 256, ATTN_SMEM>>>(Qhb, Qlb, Khb, Klb, Vhb, Vlb, Ob);

    // output projection (3xTF32)
    tf32x3_gemm_kernel<<<dim3(DM / 128, M_ / 128), 256, GEMM_SMEM>>>(Ob, Wo, out, M_, DM, DM);
}

// round 16
// speedup vs baseline: 1.8913x; 1.6810x over previous
#include <cuda_runtime.h>
#include <cuda_bf16.h>
#include <math.h>
#include <mma.h>

using namespace nvcuda;

#define B_   2
#define S_   2048
#define DM   4096
#define NH   32
#define NKV  8
#define HD   128
#define GRP  4
#define M_   (B_ * S_)        // 4096
#define KVDIM (NKV * HD)      // 1024

// ---------------- scratch (device globals; no allocation allowed) ----------
__device__ float g_Q [(size_t)M_ * DM];     // 64 MB (proj out, pre-rope)
__device__ float g_K [(size_t)M_ * KVDIM];  // 16 MB
__device__ float g_V [(size_t)M_ * KVDIM];  // 16 MB
__device__ float g_O [(size_t)M_ * DM];     // 64 MB (attention out)
__device__ float g_Qh[(size_t)M_ * DM];     // 64 MB  roped Q, tf32 hi
__device__ float g_Ql[(size_t)M_ * DM];     // 64 MB  roped Q, tf32 lo
__device__ float g_Kh[(size_t)M_ * KVDIM];  // 16 MB
__device__ float g_Kl[(size_t)M_ * KVDIM];  // 16 MB
__device__ float g_Vh[(size_t)M_ * KVDIM];  // 16 MB
__device__ float g_Vl[(size_t)M_ * KVDIM];  // 16 MB

__device__ __forceinline__ void tf32_split(float x, float& hi, float& lo) {
    hi = wmma::__float_to_tf32(x);
    lo = wmma::__float_to_tf32(x - hi);
}

__device__ __forceinline__ void bf16_split(float x, __nv_bfloat16& h, __nv_bfloat16& l) {
    h = __float2bfloat16(x);
    l = __float2bfloat16(x - __bfloat162float(h));
}

// ---------------- bf16x3 GEMM: C[M,N] = A[M,K] @ B[K,N], row-major ---------
// 128x128 CTA tile, BK=16, 256 threads (8 warps as 2x4), warp tile 64x32.
// bf16 hi/lo split staged in smem; 3 MMAs (AhBh + AhBl + AlBh) per tile pair,
// one m16n16k16 ks-step per K-tile (vs two k8 steps for tf32).
#define GA_LD 24               // A row stride in bf16 elements (16 -> 24 pad)
#define GB_LD 136              // B row stride in bf16 elements (128 -> 136 pad)
#define GA_PART (128 * GA_LD)  // bf16 elements per A buffer part
#define GB_PART (16 * GB_LD)   // bf16 elements per B buffer part
#define GEMM_SMEM ((2 * GA_PART * 2 + 2 * GB_PART * 2) * 2)   // 41984 B

__global__ __launch_bounds__(256)
void bf16x3_gemm_kernel(const float* __restrict__ A, const float* __restrict__ B,
                        float* __restrict__ C, int M, int N, int K)
{
    extern __shared__ __align__(128) __nv_bfloat16 dynsmh[];
    __nv_bfloat16* Ah = dynsmh;               // [2][128][GA_LD]
    __nv_bfloat16* Al = Ah + 2 * GA_PART;
    __nv_bfloat16* Bh = Al + 2 * GA_PART;     // [2][16][GB_LD]
    __nv_bfloat16* Bl = Bh + 2 * GB_PART;

    const int tid  = threadIdx.x;
    const int warp = tid >> 5;
    const int wm   = warp >> 2;           // 0..1
    const int wn   = warp & 3;            // 0..3
    const int colBase = blockIdx.x * 128;
    const int rowBase = blockIdx.y * 128;

    const int a_r0 = (tid)       >> 2, a_c0 = ((tid)       & 3) << 2;
    const int a_r1 = (tid + 256) >> 2, a_c1 = ((tid + 256) & 3) << 2;
    const int b_r0 = (tid)       >> 5, b_c0 = ((tid)       & 31) << 2;
    const int b_r1 = (tid + 256) >> 5, b_c1 = ((tid + 256) & 31) << 2;

    wmma::fragment<wmma::accumulator, 16, 16, 16, float> acc[4][2];
#pragma unroll
    for (int i = 0; i < 4; i++)
#pragma unroll
        for (int j = 0; j < 2; j++) wmma::fill_fragment(acc[i][j], 0.0f);

    float4 aV0, aV1, bV0, bV1;

    // split one float4 into hi/lo bf16 smem (two bf16x2 stores per array)
#define SPLIT4(dstH, dstL, off, v) do {                                       \
        __nv_bfloat16 h0,l0,h1,l1,h2,l2,h3,l3;                                 \
        bf16_split((v).x, h0, l0); bf16_split((v).y, h1, l1);                  \
        bf16_split((v).z, h2, l2); bf16_split((v).w, h3, l3);                  \
        *(__nv_bfloat162*)((dstH) + (off)    ) = __nv_bfloat162(h0, h1);       \
        *(__nv_bfloat162*)((dstH) + (off) + 2) = __nv_bfloat162(h2, h3);       \
        *(__nv_bfloat162*)((dstL) + (off)    ) = __nv_bfloat162(l0, l1);       \
        *(__nv_bfloat162*)((dstL) + (off) + 2) = __nv_bfloat162(l2, l3);       \
    } while (0)

    // prologue: tile 0 -> buffer 0
    aV0 = *(const float4*)(A + (size_t)(rowBase + a_r0) * K + a_c0);
    aV1 = *(const float4*)(A + (size_t)(rowBase + a_r1) * K + a_c1);
    bV0 = *(const float4*)(B + (size_t)b_r0 * N + colBase + b_c0);
    bV1 = *(const float4*)(B + (size_t)b_r1 * N + colBase + b_c1);
    SPLIT4(Ah, Al, a_r0 * GA_LD + a_c0, aV0);
    SPLIT4(Ah, Al, a_r1 * GA_LD + a_c1, aV1);
    SPLIT4(Bh, Bl, b_r0 * GB_LD + b_c0, bV0);
    SPLIT4(Bh, Bl, b_r1 * GB_LD + b_c1, bV1);
    __syncthreads();

    int buf = 0;
    const int nkt = K >> 4;
    for (int kt = 0; kt < nkt; kt++) {
        const int k1 = (kt + 1) << 4;
        const bool more = (kt + 1 < nkt);
        if (more) {   // prefetch next tile (overlaps mma)
            aV0 = *(const float4*)(A + (size_t)(rowBase + a_r0) * K + k1 + a_c0);
            aV1 = *(const float4*)(A + (size_t)(rowBase + a_r1) * K + k1 + a_c1);
            bV0 = *(const float4*)(B + (size_t)(k1 + b_r0) * N + colBase + b_c0);
            bV1 = *(const float4*)(B + (size_t)(k1 + b_r1) * N + colBase + b_c1);
        }
        {
            const int aOff = buf * GA_PART + (wm * 64) * GA_LD;
            const int bOff = buf * GB_PART + wn * 32;
            wmma::fragment<wmma::matrix_a, 16, 16, 16, __nv_bfloat16, wmma::row_major> afh[4], afl[4];
            wmma::fragment<wmma::matrix_b, 16, 16, 16, __nv_bfloat16, wmma::row_major> bfh[2], bfl[2];
#pragma unroll
            for (int i = 0; i < 4; i++) {
                wmma::load_matrix_sync(afh[i], Ah + aOff + i * 16 * GA_LD, GA_LD);
                wmma::load_matrix_sync(afl[i], Al + aOff + i * 16 * GA_LD, GA_LD);
            }
#pragma unroll
            for (int j = 0; j < 2; j++) {
                wmma::load_matrix_sync(bfh[j], Bh + bOff + j * 16, GB_LD);
                wmma::load_matrix_sync(bfl[j], Bl + bOff + j * 16, GB_LD);
            }
#pragma unroll
            for (int i = 0; i < 4; i++)
#pragma unroll
                for (int j = 0; j < 2; j++) {
                    wmma::mma_sync(acc[i][j], afh[i], bfh[j], acc[i][j]);
                    wmma::mma_sync(acc[i][j], afh[i], bfl[j], acc[i][j]);
                    wmma::mma_sync(acc[i][j], afl[i], bfh[j], acc[i][j]);
                }
        }
        if (more) {
            const int nb = buf ^ 1;
            SPLIT4(Ah, Al, nb * GA_PART + a_r0 * GA_LD + a_c0, aV0);
            SPLIT4(Ah, Al, nb * GA_PART + a_r1 * GA_LD + a_c1, aV1);
            SPLIT4(Bh, Bl, nb * GB_PART + b_r0 * GB_LD + b_c0, bV0);
            SPLIT4(Bh, Bl, nb * GB_PART + b_r1 * GB_LD + b_c1, bV1);
            __syncthreads();
            buf = nb;
        }
    }
#undef SPLIT4

#pragma unroll
    for (int i = 0; i < 4; i++)
#pragma unroll
        for (int j = 0; j < 2; j++)
            wmma::store_matrix_sync(
                C + (size_t)(rowBase + wm * 64 + i * 16) * N + colBase + wn * 32 + j * 16,
                acc[i][j], N, wmma::mem_row_major);
}

// ---------------- RoPE + tf32 hi/lo split ----------------------------------
__global__ void rope_split_kernel(const float* __restrict__ src,
                                  float* __restrict__ dstH, float* __restrict__ dstL,
                                  int ld, int nheads, int total)
{
    int idx = blockIdx.x * blockDim.x + threadIdx.x;
    if (idx >= total) return;
    int i   = idx & 63;
    int t   = idx >> 6;
    int h   = t % nheads;
    int row = t / nheads;
    int s   = row & (S_ - 1);

    float inv = powf(10000.0f, -(float)i * (1.0f / 64.0f));
    float ang = (float)s * inv;
    float sn, cs;
    sincosf(ang, &sn, &cs);

    size_t base = (size_t)row * ld + h * HD + i;
    float x1 = src[base], x2 = src[base + 64];
    float r1 = x1 * cs - x2 * sn;
    float r2 = x2 * cs + x1 * sn;
    float h1, l1, h2, l2;
    tf32_split(r1, h1, l1);
    tf32_split(r2, h2, l2);
    dstH[base] = h1;  dstL[base] = l1;
    dstH[base + 64] = h2;  dstL[base + 64] = l2;
}

// ---------------- plain tf32 hi/lo split (for V) ----------------------------
__global__ void split_kernel(const float* __restrict__ src,
                             float* __restrict__ dstH, float* __restrict__ dstL,
                             int total)
{
    int idx = blockIdx.x * blockDim.x + threadIdx.x;
    if (idx >= total) return;
    float h, l;
    tf32_split(src[idx], h, l);
    dstH[idx] = h;
    dstL[idx] = l;
}

// ---------------- 3xTF32 wmma flash attention, smem-staged ------------------
// (unchanged from R11 passing kernel — bit-exact)
#define QS_LD 132
#define PS_LD 68
#define OS_LD 128
#define ATTN_SMEM ((4 * 64 * QS_LD + 64 * PS_LD + 64 * OS_LD) * 4)   // 185344 B

__global__ __launch_bounds__(256)
void attn_kernel(const float* __restrict__ Qh, const float* __restrict__ Ql,
                 const float* __restrict__ Kh, const float* __restrict__ Kl,
                 const float* __restrict__ Vh, const float* __restrict__ Vl,
                 float* __restrict__ O)
{
    extern __shared__ __align__(256) float dynsm[];
    float* Qsh = dynsm;                  // [64][QS_LD]
    float* Qsl = Qsh + 64 * QS_LD;       // [64][QS_LD]
    float* KVh = Qsl + 64 * QS_LD;       // [64][QS_LD]  K tile, then V tile
    float* KVl = KVh + 64 * QS_LD;       // [64][QS_LD]
    float* Ps  = KVl + 64 * QS_LD;       // [64][PS_LD]
    float* Os  = Ps  + 64 * PS_LD;       // [64][OS_LD]

    const int qt  = gridDim.x - 1 - blockIdx.x;   // heavy tiles first
    const int q0  = qt * 64;
    const int h   = blockIdx.y;
    const int b   = blockIdx.z;
    const int kvh = h / GRP;
    const int tid = threadIdx.x;
    const int w   = tid >> 5;
    const int wr  = w >> 1;            // 0..3
    const int wc  = w & 1;             // 0..1

    const int srow = tid >> 2;         // softmax row 0..63
    const int sgrp = tid & 3;          // 4 threads per row

    const float scale = 0.08838834764831845f;  // 128^-0.5

    const size_t kvoff = (size_t)(b * S_) * KVDIM + kvh * HD;
    const float* Khp = Kh + kvoff;
    const float* Klp = Kl + kvoff;
    const float* Vhp = Vh + kvoff;
    const float* Vlp = Vl + kvoff;

    const int ld_row = tid >> 2;             // 0..63
    const int ld_c0  = (tid & 3) << 5;       // 0,32,64,96

    // ---- stage Q hi/lo once (coalesced) ----
    {
        const size_t qgbase = (size_t)(b * S_ + q0 + ld_row) * DM + h * HD + ld_c0;
#pragma unroll
        for (int u = 0; u < 8; u++) {
            *(float4*)(Qsh + ld_row * QS_LD + ld_c0 + u * 4) =
                *(const float4*)(Qh + qgbase + u * 4);
            *(float4*)(Qsl + ld_row * QS_LD + ld_c0 + u * 4) =
                *(const float4*)(Ql + qgbase + u * 4);
        }
    }
    for (int i = tid; i < 64 * OS_LD; i += 256) Os[i] = 0.f;
    __syncthreads();

    float mrow = -INFINITY, lrow = 0.f;

    const int nkt = qt + 1;
    for (int kt = 0; kt < nkt; kt++) {
        const int c0 = kt * 64;

        // ---- stage K tile hi/lo (coalesced) ----
        {
            const size_t kgbase = (size_t)(c0 + ld_row) * KVDIM + ld_c0;
#pragma unroll
            for (int u = 0; u < 8; u++) {
                *(float4*)(KVh + ld_row * QS_LD + ld_c0 + u * 4) =
                    *(const float4*)(Khp + kgbase + u * 4);
                *(float4*)(KVl + ld_row * QS_LD + ld_c0 + u * 4) =
                    *(const float4*)(Klp + kgbase + u * 4);
            }
        }
        __syncthreads();

        // ---- scores: S[64x64] = Q Ktile^T, 3xTF32 (fragments from smem) ----
        {
            wmma::fragment<wmma::accumulator, 16, 16, 8, float> sacc[2];
            wmma::fill_fragment(sacc[0], 0.f);
            wmma::fill_fragment(sacc[1], 0.f);
#pragma unroll
            for (int d0 = 0; d0 < HD; d0 += 8) {
                wmma::fragment<wmma::matrix_a, 16, 16, 8, wmma::precision::tf32, wmma::row_major> afh, afl;
                wmma::load_matrix_sync(afh, Qsh + (wr * 16) * QS_LD + d0, QS_LD);
                wmma::load_matrix_sync(afl, Qsl + (wr * 16) * QS_LD + d0, QS_LD);
#pragma unroll
                for (int j = 0; j < 2; j++) {
                    wmma::fragment<wmma::matrix_b, 16, 16, 8, wmma::precision::tf32, wmma::col_major> bfh, bfl;
                    const int ko = (wc * 32 + j * 16) * QS_LD + d0;
                    wmma::load_matrix_sync(bfh, KVh + ko, QS_LD);
                    wmma::load_matrix_sync(bfl, KVl + ko, QS_LD);
                    wmma::mma_sync(sacc[j], afh, bfh, sacc[j]);
                    wmma::mma_sync(sacc[j], afh, bfl, sacc[j]);
                    wmma::mma_sync(sacc[j], afl, bfh, sacc[j]);
                }
            }
#pragma unroll
            for (int j = 0; j < 2; j++)
                wmma::store_matrix_sync(&Ps[(wr * 16) * PS_LD + wc * 32 + j * 16],
                                        sacc[j], PS_LD, wmma::mem_row_major);
        }
        __syncthreads();

        // ---- softmax (SIMT, online): 4 threads per row, 16 cols each ----
        {
            const bool diag = (kt == nkt - 1);
            float sv[16];
            float* prow = &Ps[srow * PS_LD + sgrp * 16];
#pragma unroll
            for (int u = 0; u < 16; u++) {
                float x = prow[u] * scale;
                if (diag && (c0 + sgrp * 16 + u > q0 + srow)) x = -INFINITY;
                sv[u] = x;
            }
            float mloc = sv[0];
#pragma unroll
            for (int u = 1; u < 16; u++) mloc = fmaxf(mloc, sv[u]);
            mloc = fmaxf(mloc, __shfl_xor_sync(0xffffffffu, mloc, 1));
            mloc = fmaxf(mloc, __shfl_xor_sync(0xffffffffu, mloc, 2));
            float mnew = fmaxf(mrow, mloc);
            float corr = __expf(mrow - mnew);
            float rs = 0.f;
#pragma unroll
            for (int u = 0; u < 16; u++) {
                float p = wmma::__float_to_tf32(__expf(sv[u] - mnew));
                prow[u] = p;
                rs += p;
            }
            rs += __shfl_xor_sync(0xffffffffu, rs, 1);
            rs += __shfl_xor_sync(0xffffffffu, rs, 2);
            lrow = lrow * corr + rs;
            mrow = mnew;
            float4* orow = (float4*)&Os[srow * OS_LD + sgrp * 32];
#pragma unroll
            for (int u = 0; u < 8; u++) {
                float4 t = orow[u];
                t.x *= corr; t.y *= corr; t.z *= corr; t.w *= corr;
                orow[u] = t;
            }
        }
        __syncthreads();   // softmax done; all QK reads of KVh/KVl done

        // ---- stage V tile hi/lo into the same buffers ----
        {
            const size_t vgbase = (size_t)(c0 + ld_row) * KVDIM + ld_c0;
#pragma unroll
            for (int u = 0; u < 8; u++) {
                *(float4*)(KVh + ld_row * QS_LD + ld_c0 + u * 4) =
                    *(const float4*)(Vhp + vgbase + u * 4);
                *(float4*)(KVl + ld_row * QS_LD + ld_c0 + u * 4) =
                    *(const float4*)(Vlp + vgbase + u * 4);
            }
        }
        __syncthreads();

        // ---- O += P @ Vtile (P tf32, V hi/lo: 2 MMAs; fragments from smem) ----
        {
            wmma::fragment<wmma::accumulator, 16, 16, 8, float> oacc[4];
#pragma unroll
            for (int j = 0; j < 4; j++)
                wmma::load_matrix_sync(oacc[j],
                    &Os[(wr * 16) * OS_LD + (w & 1) * 64 + j * 16], OS_LD,
                    wmma::mem_row_major);
#pragma unroll
            for (int kk = 0; kk < 64; kk += 8) {
                wmma::fragment<wmma::matrix_a, 16, 16, 8, wmma::precision::tf32, wmma::row_major> pa;
                wmma::load_matrix_sync(pa, &Ps[(wr * 16) * PS_LD + kk], PS_LD);
#pragma unroll
                for (int j = 0; j < 4; j++) {
                    wmma::fragment<wmma::matrix_b, 16, 16, 8, wmma::precision::tf32, wmma::row_major> vbh, vbl;
                    const int vo = kk * QS_LD + (w & 1) * 64 + j * 16;
                    wmma::load_matrix_sync(vbh, KVh + vo, QS_LD);
                    wmma::load_matrix_sync(vbl, KVl + vo, QS_LD);
                    wmma::mma_sync(oacc[j], pa, vbh, oacc[j]);
                    wmma::mma_sync(oacc[j], pa, vbl, oacc[j]);
                }
            }
#pragma unroll
            for (int j = 0; j < 4; j++)
                wmma::store_matrix_sync(
                    &Os[(wr * 16) * OS_LD + (w & 1) * 64 + j * 16], oacc[j], OS_LD,
                    wmma::mem_row_major);
        }
        __syncthreads();   // PV reads of KVh/KVl done
    }

    // ---- normalize + store O in [b*s, h*128+d] layout ----
    {
        float inv = 1.0f / lrow;
        float* dst = O + (size_t)(b * S_ + q0 + srow) * DM + h * HD + sgrp * 32;
        float4* orow = (float4*)&Os[srow * OS_LD + sgrp * 32];
#pragma unroll
        for (int u = 0; u < 8; u++) {
            float4 t = orow[u];
            t.x *= inv; t.y *= inv; t.z *= inv; t.w *= inv;
            ((float4*)dst)[u] = t;
        }
    }
}

// ---------------- launch ----------------------------------------------------
extern "C" void kernel_launch(void* const* d_in, const int* in_sizes, int n_in,
                              void* d_out, int out_size)
{
    const float* x  = (const float*)d_in[0];
    // d_in[1] = mask (deterministic causal triu; computed analytically instead)
    const float* Wq = (const float*)d_in[2];
    const float* Wk = (const float*)d_in[3];
    const float* Wv = (const float*)d_in[4];
    const float* Wo = (const float*)d_in[5];
    float* out = (float*)d_out;

    float *Qb, *Kb, *Vb, *Ob, *Qhb, *Qlb, *Khb, *Klb, *Vhb, *Vlb;
    cudaGetSymbolAddress((void**)&Qb,  g_Q);
    cudaGetSymbolAddress((void**)&Kb,  g_K);
    cudaGetSymbolAddress((void**)&Vb,  g_V);
    cudaGetSymbolAddress((void**)&Ob,  g_O);
    cudaGetSymbolAddress((void**)&Qhb, g_Qh);
    cudaGetSymbolAddress((void**)&Qlb, g_Ql);
    cudaGetSymbolAddress((void**)&Khb, g_Kh);
    cudaGetSymbolAddress((void**)&Klb, g_Kl);
    cudaGetSymbolAddress((void**)&Vhb, g_Vh);
    cudaGetSymbolAddress((void**)&Vlb, g_Vl);

    static bool attrs_set = false;
    if (!attrs_set) {   // host-side state, not stream work; capture-safe
        cudaFuncSetAttribute(attn_kernel,
                             cudaFuncAttributeMaxDynamicSharedMemorySize, ATTN_SMEM);
        cudaFuncSetAttribute(bf16x3_gemm_kernel,
                             cudaFuncAttributeMaxDynamicSharedMemorySize, GEMM_SMEM);
        attrs_set = true;
    }

    // projections (bf16x3 split tensor cores, m16n16k16)
    bf16x3_gemm_kernel<<<dim3(DM / 128, M_ / 128), 256, GEMM_SMEM>>>(x, Wq, Qb, M_, DM, DM);
    bf16x3_gemm_kernel<<<dim3(KVDIM / 128, M_ / 128), 256, GEMM_SMEM>>>(x, Wk, Kb, M_, KVDIM, DM);
    bf16x3_gemm_kernel<<<dim3(KVDIM / 128, M_ / 128), 256, GEMM_SMEM>>>(x, Wv, Vb, M_, KVDIM, DM);

    // RoPE + hi/lo split; V split (tf32 splits for attention, unchanged)
    {
        int totQ = M_ * NH * 64;
        rope_split_kernel<<<(totQ + 255) / 256, 256>>>(Qb, Qhb, Qlb, DM, NH, totQ);
        int totK = M_ * NKV * 64;
        rope_split_kernel<<<(totK + 255) / 256, 256>>>(Kb, Khb, Klb, KVDIM, NKV, totK);
        int totV = M_ * KVDIM;
        split_kernel<<<(totV + 255) / 256, 256>>>(Vb, Vhb, Vlb, totV);
    }

    // causal GQA attention (3xTF32, smem-staged — unchanged from R11)
    attn_kernel<<<dim3(S_ / 64, NH, B_), 256, ATTN_SMEM>>>(Qhb, Qlb, Khb, Klb, Vhb, Vlb, Ob);

    // output projection (bf16x3)
    bf16x3_gemm_kernel<<<dim3(DM / 128, M_ / 128), 256, GEMM_SMEM>>>(Ob, Wo, out, M_, DM, DM);
}